// round 1
// baseline (speedup 1.0000x reference)
#include <cuda_runtime.h>

#define NN 10000     // nodes
#define KD 8         // out-degree
#define EE 80000     // edges
#define HDIM 512     // H*D

// Scratch (allocation-free rule: __device__ globals)
__device__ float g_nq[NN * HDIM];
__device__ float g_nk[NN * HDIM];
__device__ float g_nv[NN * HDIM];
__device__ float g_node[NN * HDIM];

// ---------------------------------------------------------------------------
// Kernel 1: one of nq/nk/nv = x @ W^T + b   ([10000,64] x [64,512])
// 64x64 output tile per block, 4x4 microtile, 256 threads.
// ---------------------------------------------------------------------------
__global__ __launch_bounds__(256) void proj_kernel(
    const float* __restrict__ X, const float* __restrict__ W,
    const float* __restrict__ b, int sel)
{
    __shared__ float As[64][65];   // [row][k]
    __shared__ float Bs[64][65];   // [col][k]
    int r0 = blockIdx.y * 64;
    int c0 = blockIdx.x * 64;
    int t  = threadIdx.x;

    #pragma unroll
    for (int i = 0; i < 4; i++) {
        int idx = t + i * 256;
        int row = idx >> 4, k4 = idx & 15;
        float4 v = make_float4(0.f, 0.f, 0.f, 0.f);
        if (r0 + row < NN) v = *(const float4*)&X[(r0 + row) * 64 + k4 * 4];
        As[row][k4*4+0] = v.x; As[row][k4*4+1] = v.y;
        As[row][k4*4+2] = v.z; As[row][k4*4+3] = v.w;
        float4 w = *(const float4*)&W[(c0 + row) * 64 + k4 * 4];
        Bs[row][k4*4+0] = w.x; Bs[row][k4*4+1] = w.y;
        Bs[row][k4*4+2] = w.z; Bs[row][k4*4+3] = w.w;
    }
    __syncthreads();

    int tx = t & 15, ty = t >> 4;
    float acc[4][4] = {};
    #pragma unroll 16
    for (int k = 0; k < 64; k++) {
        float a[4], bb[4];
        #pragma unroll
        for (int i = 0; i < 4; i++) a[i] = As[ty * 4 + i][k];
        #pragma unroll
        for (int j = 0; j < 4; j++) bb[j] = Bs[tx * 4 + j][k];
        #pragma unroll
        for (int i = 0; i < 4; i++)
            #pragma unroll
            for (int j = 0; j < 4; j++)
                acc[i][j] = fmaf(a[i], bb[j], acc[i][j]);
    }

    float* outp = (sel == 0) ? g_nq : (sel == 1) ? g_nk : g_nv;
    #pragma unroll
    for (int i = 0; i < 4; i++) {
        int row = r0 + ty * 4 + i;
        if (row < NN) {
            #pragma unroll
            for (int j = 0; j < 4; j++) {
                int c = c0 + tx * 4 + j;
                outp[row * HDIM + c] = acc[i][j] + b[c];
            }
        }
    }
}

// ---------------------------------------------------------------------------
// Kernel 2: fully fused per-node pipeline. One block = one node (its 8 edges).
//   sqk -> eq/ev/ek -> 8x8 edge-edge attention -> edge_emb
//   -> edge_embeddings output, node softmax, nv aggregation -> g_node
// ---------------------------------------------------------------------------
__global__ __launch_bounds__(256) void node_edge_kernel(
    const float* __restrict__ edge_features,
    const int*   __restrict__ edge_index,
    const float* __restrict__ Weq, const float* __restrict__ beq,
    const float* __restrict__ Wev, const float* __restrict__ bev,
    const float* __restrict__ Wek, const float* __restrict__ bek,
    const float* __restrict__ Wel, const float* __restrict__ bel,
    const float* __restrict__ Wele, const float* __restrict__ bele,
    float* __restrict__ out_edge)
{
    int n = blockIdx.x;
    int t = threadIdx.x;

    __shared__ __align__(16) float s_nq[512];
    __shared__ __align__(16) float s_ef[128];     // 8 edges x 16 feats (contiguous)
    __shared__ float s_sqk[8][8];                 // [edge][h]
    __shared__ float s_eq[8][64];
    __shared__ float s_ev[8][64];
    __shared__ float s_ek[8][64];
    __shared__ float s_att[8][4][8];              // [q][eh][k]
    __shared__ float s_eout[8][64];
    __shared__ float s_ee[8][8];                  // edge_emb [edge][h]
    __shared__ float s_attn[8][8];                // node att [edge][h]
    __shared__ int   s_e1[8];

    if (t < 8)  s_e1[t] = edge_index[EE + n * 8 + t];     // row1 (targets)
    if (t < 128) {
        ((float4*)s_nq)[t] = ((const float4*)g_nq)[n * 128 + t];
        s_ef[t] = edge_features[n * 128 + t];
    }
    __syncthreads();

    // ---- sqk[j][h] = <nq[n,h,:], nk[e1[j],h,:]> / 8 : 64 pairs x 4 threads ----
    {
        int g = t >> 2, l4 = t & 3;
        int j = g >> 3, h = g & 7;
        const float4* nk4 = (const float4*)g_nk;
        const float4* q4  = (const float4*)s_nq;
        int qb = h * 16 + l4 * 4;
        long kb = (long)s_e1[j] * 128 + h * 16 + l4 * 4;
        float sum = 0.f;
        #pragma unroll
        for (int i = 0; i < 4; i++) {
            float4 a = q4[qb + i];
            float4 b = __ldg(&nk4[kb + i]);
            sum += a.x * b.x + a.y * b.y + a.z * b.z + a.w * b.w;
        }
        sum += __shfl_xor_sync(0xffffffffu, sum, 1);
        sum += __shfl_xor_sync(0xffffffffu, sum, 2);
        if (l4 == 0) s_sqk[j][h] = sum * 0.125f;   // / sqrt(64)
    }
    __syncthreads();

    // ---- eq, ev (from edge feats), ek (from sqk): 512 outputs each ----
    #pragma unroll
    for (int r = 0; r < 2; r++) {
        int idx = t + r * 256;
        int j = idx >> 6, o = idx & 63;
        const float4* ef4 = (const float4*)&s_ef[j * 16];
        const float4* wq4 = (const float4*)&Weq[o * 16];
        const float4* wv4 = (const float4*)&Wev[o * 16];
        float aq = beq[o], av = bev[o];
        #pragma unroll
        for (int c = 0; c < 4; c++) {
            float4 f = ef4[c];
            float4 wq = __ldg(&wq4[c]);
            float4 wv = __ldg(&wv4[c]);
            aq += f.x * wq.x + f.y * wq.y + f.z * wq.z + f.w * wq.w;
            av += f.x * wv.x + f.y * wv.y + f.z * wv.z + f.w * wv.w;
        }
        s_eq[j][o] = aq;
        s_ev[j][o] = av;
        float ae = bek[o];
        const float4* wk4 = (const float4*)&Wek[o * 8];
        float4 w0 = __ldg(&wk4[0]), w1 = __ldg(&wk4[1]);
        ae += s_sqk[j][0] * w0.x + s_sqk[j][1] * w0.y + s_sqk[j][2] * w0.z + s_sqk[j][3] * w0.w;
        ae += s_sqk[j][4] * w1.x + s_sqk[j][5] * w1.y + s_sqk[j][6] * w1.z + s_sqk[j][7] * w1.w;
        s_ek[j][o] = ae;
    }
    __syncthreads();

    // ---- edge-edge attention: warp = query edge q; lane: eh = lane/8, k = lane%8 ----
    {
        int q = t >> 5;
        int lane = t & 31;
        int eh = lane >> 3, k = lane & 7;
        float s = 0.f;
        #pragma unroll
        for (int de = 0; de < 16; de++)
            s += s_eq[q][eh * 16 + de] * s_ek[k][eh * 16 + de];
        s *= 0.25f;                                   // / sqrt(16)
        float mx = s;
        mx = fmaxf(mx, __shfl_xor_sync(0xffffffffu, mx, 1));
        mx = fmaxf(mx, __shfl_xor_sync(0xffffffffu, mx, 2));
        mx = fmaxf(mx, __shfl_xor_sync(0xffffffffu, mx, 4));
        float ex = expf(s - mx);
        float sm = ex;
        sm += __shfl_xor_sync(0xffffffffu, sm, 1);
        sm += __shfl_xor_sync(0xffffffffu, sm, 2);
        sm += __shfl_xor_sync(0xffffffffu, sm, 4);
        s_att[q][eh][k] = ex / (sm + 1e-16f);
    }
    __syncthreads();

    // ---- eout[q][eh*16+de] = sum_k att * ev[k] ----
    #pragma unroll
    for (int r = 0; r < 2; r++) {
        int idx = t + r * 256;
        int q = idx >> 6, o = idx & 63;
        int eh = o >> 4;
        float acc = 0.f;
        #pragma unroll
        for (int k = 0; k < 8; k++)
            acc += s_att[q][eh][k] * s_ev[k][o];
        s_eout[q][o] = acc;
    }
    __syncthreads();

    // ---- edge_emb[q][h] = eout[q] . Wel[h] + bel[h] ----
    if (t < 64) {
        int q = t >> 3, h = t & 7;
        float acc = bel[h];
        const float4* w4 = (const float4*)&Wel[h * 64];
        const float4* e4 = (const float4*)&s_eout[q][0];
        #pragma unroll
        for (int c = 0; c < 16; c++) {
            float4 w = __ldg(&w4[c]);
            float4 e = e4[c];
            acc += e.x * w.x + e.y * w.y + e.z * w.z + e.w * w.w;
        }
        s_ee[q][h] = acc;
    }
    __syncthreads();

    // ---- node softmax over the 8 edges (per h), and edge_embeddings output ----
    if (t < 8) {
        int h = t;
        float l[8], mx = -1e30f;
        #pragma unroll
        for (int j = 0; j < 8; j++) { l[j] = s_ee[j][h] + s_sqk[j][h]; mx = fmaxf(mx, l[j]); }
        float sm = 0.f;
        #pragma unroll
        for (int j = 0; j < 8; j++) { l[j] = expf(l[j] - mx); sm += l[j]; }
        float inv = 1.f / (sm + 1e-16f);
        #pragma unroll
        for (int j = 0; j < 8; j++) s_attn[j][h] = l[j] * inv;
    }
    if (t >= 128) {
        int idx = t - 128;
        int q = idx >> 4, de = idx & 15;
        float acc = bele[de];
        #pragma unroll
        for (int h = 0; h < 8; h++)
            acc += s_ee[q][h] * __ldg(&Wele[de * 8 + h]);
        out_edge[(n * 8 + q) * 16 + de] = acc;
    }
    __syncthreads();

    // ---- node aggregation: g_node[n, o] = sum_j attn[j][h] * nv[e1[j], o] ----
    #pragma unroll
    for (int r = 0; r < 2; r++) {
        int o = t + r * 256;
        int h = o >> 6;
        float acc = 0.f;
        #pragma unroll
        for (int j = 0; j < 8; j++)
            acc += s_attn[j][h] * __ldg(&g_nv[(long)s_e1[j] * HDIM + o]);
        g_node[n * HDIM + o] = acc;
    }
}

// ---------------------------------------------------------------------------
// Kernel 3: node_embeddings = g_node[10000,512] @ Wlin^T[512,64] + blin
// ---------------------------------------------------------------------------
__global__ __launch_bounds__(256) void out_gemm_kernel(
    const float* __restrict__ Wlin, const float* __restrict__ blin,
    float* __restrict__ out)
{
    __shared__ float As[64][65];
    __shared__ float Ws[64][65];
    int r0 = blockIdx.x * 64;
    int t  = threadIdx.x;
    int tx = t & 15, ty = t >> 4;
    float acc[4][4] = {};

    for (int k0 = 0; k0 < 512; k0 += 64) {
        __syncthreads();
        #pragma unroll
        for (int i = 0; i < 4; i++) {
            int idx = t + i * 256;
            int row = idx >> 4, k4 = idx & 15;
            float4 v = make_float4(0.f, 0.f, 0.f, 0.f);
            if (r0 + row < NN) v = *(const float4*)&g_node[(r0 + row) * 512 + k0 + k4 * 4];
            As[row][k4*4+0] = v.x; As[row][k4*4+1] = v.y;
            As[row][k4*4+2] = v.z; As[row][k4*4+3] = v.w;
            float4 w = *(const float4*)&Wlin[row * 512 + k0 + k4 * 4];  // row = output dim d
            Ws[row][k4*4+0] = w.x; Ws[row][k4*4+1] = w.y;
            Ws[row][k4*4+2] = w.z; Ws[row][k4*4+3] = w.w;
        }
        __syncthreads();
        #pragma unroll 16
        for (int k = 0; k < 64; k++) {
            float a[4], b[4];
            #pragma unroll
            for (int i = 0; i < 4; i++) a[i] = As[ty * 4 + i][k];
            #pragma unroll
            for (int j = 0; j < 4; j++) b[j] = Ws[tx * 4 + j][k];
            #pragma unroll
            for (int i = 0; i < 4; i++)
                #pragma unroll
                for (int j = 0; j < 4; j++)
                    acc[i][j] = fmaf(a[i], b[j], acc[i][j]);
        }
    }

    #pragma unroll
    for (int i = 0; i < 4; i++) {
        int row = r0 + ty * 4 + i;
        if (row < NN) {
            #pragma unroll
            for (int j = 0; j < 4; j++) {
                int d = tx * 4 + j;
                out[row * 64 + d] = acc[i][j] + blin[d];
            }
        }
    }
}

// ---------------------------------------------------------------------------
extern "C" void kernel_launch(void* const* d_in, const int* in_sizes, int n_in,
                              void* d_out, int out_size)
{
    const float* x    = (const float*)d_in[0];
    const float* ef   = (const float*)d_in[1];
    const float* Wq   = (const float*)d_in[2];
    const float* bq   = (const float*)d_in[3];
    const float* Wk   = (const float*)d_in[4];
    const float* bk   = (const float*)d_in[5];
    const float* Wv   = (const float*)d_in[6];
    const float* bv   = (const float*)d_in[7];
    const float* Wlin = (const float*)d_in[8];
    const float* blin = (const float*)d_in[9];
    const float* Weq  = (const float*)d_in[10];
    const float* beq  = (const float*)d_in[11];
    const float* Wev  = (const float*)d_in[12];
    const float* bev  = (const float*)d_in[13];
    const float* Wek  = (const float*)d_in[14];
    const float* bek  = (const float*)d_in[15];
    const float* Wel  = (const float*)d_in[16];
    const float* bel  = (const float*)d_in[17];
    const float* Wele = (const float*)d_in[18];
    const float* bele = (const float*)d_in[19];
    const int*   eidx = (const int*)d_in[20];
    float* out = (float*)d_out;

    dim3 g1(8, 157);   // 512 cols / 64, ceil(10000/64)
    proj_kernel<<<g1, 256>>>(x, Wq, bq, 0);
    proj_kernel<<<g1, 256>>>(x, Wk, bk, 1);
    proj_kernel<<<g1, 256>>>(x, Wv, bv, 2);
    node_edge_kernel<<<NN, 256>>>(ef, eidx, Weq, beq, Wev, bev, Wek, bek,
                                  Wel, bel, Wele, bele, out + NN * 64);
    out_gemm_kernel<<<157, 256>>>(Wlin, blin, out);
}

// round 2
// speedup vs baseline: 1.2371x; 1.2371x over previous
#include <cuda_runtime.h>

#define NN 10000     // nodes
#define KD 8         // out-degree
#define EE 80000     // edges
#define HDIM 512     // H*D

// Scratch (allocation-free rule: __device__ globals)
__device__ float g_nq[NN * HDIM];
__device__ float g_nk[NN * HDIM];
__device__ float g_nv[NN * HDIM];
__device__ float g_node[NN * HDIM];

// ---- packed f32x2 helpers (FFMA2 path: only reachable via PTX) ----
__device__ __forceinline__ unsigned long long pack2(float lo, float hi) {
    unsigned long long r;
    asm("mov.b64 %0, {%1, %2};" : "=l"(r) : "f"(lo), "f"(hi));
    return r;
}
__device__ __forceinline__ void ffma2(unsigned long long& d,
                                      unsigned long long a,
                                      unsigned long long b) {
    asm("fma.rn.f32x2 %0, %1, %2, %0;" : "+l"(d) : "l"(a), "l"(b));
}
__device__ __forceinline__ float2 unpack2(unsigned long long v) {
    float2 f;
    asm("mov.b64 {%0, %1}, %2;" : "=f"(f.x), "=f"(f.y) : "l"(v));
    return f;
}

// ---------------------------------------------------------------------------
// Kernel 1: fused QKV projection.  out = X[10000,64] @ W^T[64,512] + b for
// W in {Wq,Wk,Wv}.  Tile 64 rows x 128 cols, microtile 4x8 (4 f32x2 pairs),
// packed-FMA inner loop.  grid = (12, 157): bx>>2 selects Q/K/V.
// ---------------------------------------------------------------------------
__global__ __launch_bounds__(256) void proj_qkv_kernel(
    const float* __restrict__ X,
    const float* __restrict__ Wq, const float* __restrict__ bq,
    const float* __restrict__ Wk, const float* __restrict__ bk,
    const float* __restrict__ Wv, const float* __restrict__ bv)
{
    __shared__ float As[64][65];     // [row][k]
    __shared__ float Bs[64][132];    // [k][col] (even stride, conflict-free pairs)

    int bx  = blockIdx.x;
    int sel = bx >> 2;
    int c0  = (bx & 3) * 128;
    int r0  = blockIdx.y * 64;
    int t   = threadIdx.x;

    const float* W    = (sel == 0) ? Wq : (sel == 1) ? Wk : Wv;
    const float* bias = (sel == 0) ? bq : (sel == 1) ? bk : bv;
    float*       outp = (sel == 0) ? g_nq : (sel == 1) ? g_nk : g_nv;

    // load X tile [64 rows x 64 k]
    #pragma unroll
    for (int i = 0; i < 4; i++) {
        int idx = t + i * 256;
        int row = idx >> 4, k4 = idx & 15;
        float4 v = make_float4(0.f, 0.f, 0.f, 0.f);
        if (r0 + row < NN) v = *(const float4*)&X[(r0 + row) * 64 + k4 * 4];
        As[row][k4*4+0] = v.x; As[row][k4*4+1] = v.y;
        As[row][k4*4+2] = v.z; As[row][k4*4+3] = v.w;
    }
    // load W tile transposed: Bs[k][col]  (col local 0..127)
    #pragma unroll
    for (int i = 0; i < 8; i++) {
        int idx = t + i * 256;            // [0, 2048)
        int c = idx >> 4, k4 = idx & 15;
        float4 w = *(const float4*)&W[(c0 + c) * 64 + k4 * 4];
        Bs[k4*4+0][c] = w.x; Bs[k4*4+1][c] = w.y;
        Bs[k4*4+2][c] = w.z; Bs[k4*4+3][c] = w.w;
    }
    __syncthreads();

    int tx = t & 15, ty = t >> 4;
    unsigned long long acc[4][4] = {};   // [row_i][pair_p], (0,0) bits == 0ULL

    #pragma unroll 8
    for (int k = 0; k < 64; k++) {
        unsigned long long a[4], b[4];
        #pragma unroll
        for (int i = 0; i < 4; i++) {
            float av = As[ty * 4 + i][k];
            a[i] = pack2(av, av);
        }
        #pragma unroll
        for (int p = 0; p < 4; p++)
            b[p] = *reinterpret_cast<const unsigned long long*>(&Bs[k][tx * 2 + 32 * p]);
        #pragma unroll
        for (int i = 0; i < 4; i++)
            #pragma unroll
            for (int p = 0; p < 4; p++)
                ffma2(acc[i][p], a[i], b[p]);
    }

    #pragma unroll
    for (int i = 0; i < 4; i++) {
        int row = r0 + ty * 4 + i;
        if (row < NN) {
            #pragma unroll
            for (int p = 0; p < 4; p++) {
                int c = c0 + tx * 2 + 32 * p;
                float2 r = unpack2(acc[i][p]);
                float2 o = make_float2(r.x + bias[c], r.y + bias[c + 1]);
                *(float2*)&outp[(long)row * HDIM + c] = o;
            }
        }
    }
}

// ---------------------------------------------------------------------------
// Kernel 2: fully fused per-node pipeline. One block = one node (its 8 edges).
// ---------------------------------------------------------------------------
__global__ __launch_bounds__(256, 5) void node_edge_kernel(
    const float* __restrict__ edge_features,
    const int*   __restrict__ edge_index,
    const float* __restrict__ Weq, const float* __restrict__ beq,
    const float* __restrict__ Wev, const float* __restrict__ bev,
    const float* __restrict__ Wek, const float* __restrict__ bek,
    const float* __restrict__ Wel, const float* __restrict__ bel,
    const float* __restrict__ Wele, const float* __restrict__ bele,
    float* __restrict__ out_edge)
{
    int n = blockIdx.x;
    int t = threadIdx.x;

    __shared__ __align__(16) float s_nq[512];
    __shared__ __align__(16) float s_ef[128];     // 8 edges x 16 feats
    __shared__ float s_sqk[8][8];                 // [edge][h]
    __shared__ float s_eq[8][64];
    __shared__ float s_ev[8][64];
    __shared__ float s_ekT[64][9];                // transposed: [eh*16+de][k], odd stride
    __shared__ float s_att[8][4][8];              // [q][eh][k]
    __shared__ __align__(16) float s_eout[8][64];
    __shared__ float s_ee[8][8];                  // edge_emb [edge][h]
    __shared__ float s_attn[8][8];                // node att [edge][h]
    __shared__ int   s_e1[8];

    if (t < 8)  s_e1[t] = edge_index[EE + n * 8 + t];     // targets
    if (t < 128) {
        ((float4*)s_nq)[t] = ((const float4*)g_nq)[n * 128 + t];
        s_ef[t] = edge_features[n * 128 + t];
    }
    __syncthreads();

    // ---- sqk[j][h] = <nq[n,h,:], nk[e1[j],h,:]> / 8 ----
    {
        int g = t >> 2, l4 = t & 3;
        int j = g >> 3, h = g & 7;
        const float4* nk4 = (const float4*)g_nk;
        const float4* q4  = (const float4*)s_nq;
        int qb = h * 16 + l4 * 4;
        long kb = (long)s_e1[j] * 128 + h * 16 + l4 * 4;
        float sum = 0.f;
        #pragma unroll
        for (int i = 0; i < 4; i++) {
            float4 a = q4[qb + i];
            float4 b = __ldg(&nk4[kb + i]);
            sum += a.x * b.x + a.y * b.y + a.z * b.z + a.w * b.w;
        }
        sum += __shfl_xor_sync(0xffffffffu, sum, 1);
        sum += __shfl_xor_sync(0xffffffffu, sum, 2);
        if (l4 == 0) s_sqk[j][h] = sum * 0.125f;   // / sqrt(64)
    }
    __syncthreads();

    // ---- eq, ev, ek projections ----
    #pragma unroll
    for (int r = 0; r < 2; r++) {
        int idx = t + r * 256;
        int j = idx >> 6, o = idx & 63;
        const float4* ef4 = (const float4*)&s_ef[j * 16];
        const float4* wq4 = (const float4*)&Weq[o * 16];
        const float4* wv4 = (const float4*)&Wev[o * 16];
        float aq = beq[o], av = bev[o];
        #pragma unroll
        for (int c = 0; c < 4; c++) {
            float4 f = ef4[c];
            float4 wq = __ldg(&wq4[c]);
            float4 wv = __ldg(&wv4[c]);
            aq += f.x * wq.x + f.y * wq.y + f.z * wq.z + f.w * wq.w;
            av += f.x * wv.x + f.y * wv.y + f.z * wv.z + f.w * wv.w;
        }
        s_eq[j][o] = aq;
        s_ev[j][o] = av;
        float ae = bek[o];
        const float4* wk4 = (const float4*)&Wek[o * 8];
        float4 w0 = __ldg(&wk4[0]), w1 = __ldg(&wk4[1]);
        ae += s_sqk[j][0] * w0.x + s_sqk[j][1] * w0.y + s_sqk[j][2] * w0.z + s_sqk[j][3] * w0.w;
        ae += s_sqk[j][4] * w1.x + s_sqk[j][5] * w1.y + s_sqk[j][6] * w1.z + s_sqk[j][7] * w1.w;
        s_ekT[o][j] = ae;                      // transposed store (conflict-free: 9 coprime 32)
    }
    __syncthreads();

    // ---- edge-edge attention: warp = query edge q; lane: eh=lane/8, k=lane%8 ----
    {
        int q = t >> 5;
        int lane = t & 31;
        int eh = lane >> 3, k = lane & 7;
        float s = 0.f;
        #pragma unroll
        for (int de = 0; de < 16; de++)
            s += s_eq[q][eh * 16 + de] * s_ekT[eh * 16 + de][k];
        s *= 0.25f;                                   // / sqrt(16)
        float mx = s;
        mx = fmaxf(mx, __shfl_xor_sync(0xffffffffu, mx, 1));
        mx = fmaxf(mx, __shfl_xor_sync(0xffffffffu, mx, 2));
        mx = fmaxf(mx, __shfl_xor_sync(0xffffffffu, mx, 4));
        float ex = expf(s - mx);
        float sm = ex;
        sm += __shfl_xor_sync(0xffffffffu, sm, 1);
        sm += __shfl_xor_sync(0xffffffffu, sm, 2);
        sm += __shfl_xor_sync(0xffffffffu, sm, 4);
        s_att[q][eh][k] = ex / (sm + 1e-16f);
    }
    __syncthreads();

    // ---- eout[q][eh*16+de] = sum_k att * ev[k] ----
    #pragma unroll
    for (int r = 0; r < 2; r++) {
        int idx = t + r * 256;
        int q = idx >> 6, o = idx & 63;
        int eh = o >> 4;
        float acc = 0.f;
        #pragma unroll
        for (int k = 0; k < 8; k++)
            acc += s_att[q][eh][k] * s_ev[k][o];
        s_eout[q][o] = acc;
    }
    __syncthreads();

    // ---- edge_emb[q][h] = eout[q] . Wel[h] + bel[h] ----
    if (t < 64) {
        int q = t >> 3, h = t & 7;
        float acc = bel[h];
        const float4* w4 = (const float4*)&Wel[h * 64];
        const float4* e4 = (const float4*)&s_eout[q][0];
        #pragma unroll
        for (int c = 0; c < 16; c++) {
            float4 w = __ldg(&w4[c]);
            float4 e = e4[c];
            acc += e.x * w.x + e.y * w.y + e.z * w.z + e.w * w.w;
        }
        s_ee[q][h] = acc;
    }
    __syncthreads();

    // ---- node softmax (t<8), edge_embeddings output (t>=128) ----
    if (t < 8) {
        int h = t;
        float l[8], mx = -1e30f;
        #pragma unroll
        for (int j = 0; j < 8; j++) { l[j] = s_ee[j][h] + s_sqk[j][h]; mx = fmaxf(mx, l[j]); }
        float sm = 0.f;
        #pragma unroll
        for (int j = 0; j < 8; j++) { l[j] = expf(l[j] - mx); sm += l[j]; }
        float inv = 1.f / (sm + 1e-16f);
        #pragma unroll
        for (int j = 0; j < 8; j++) s_attn[j][h] = l[j] * inv;
    }
    if (t >= 128) {
        int idx = t - 128;
        int q = idx >> 4, de = idx & 15;
        float acc = bele[de];
        #pragma unroll
        for (int h = 0; h < 8; h++)
            acc += s_ee[q][h] * __ldg(&Wele[de * 8 + h]);
        out_edge[(n * 8 + q) * 16 + de] = acc;
    }
    __syncthreads();

    // ---- node aggregation (float2-vectorized): g_node[n, 2t..2t+1] ----
    {
        int h = t >> 5;                               // (2t)>>6
        float2 acc = make_float2(0.f, 0.f);
        #pragma unroll
        for (int j = 0; j < 8; j++) {
            float w = s_attn[j][h];
            float2 v = __ldg((const float2*)&g_nv[(long)s_e1[j] * HDIM + 2 * t]);
            acc.x = fmaf(w, v.x, acc.x);
            acc.y = fmaf(w, v.y, acc.y);
        }
        *(float2*)&g_node[(long)n * HDIM + 2 * t] = acc;
    }
}

// ---------------------------------------------------------------------------
// Kernel 3: node_embeddings = g_node[10000,512] @ Wlin^T[512,64] + blin
// f32x2 packed FMA, 64x64 tile, 4x4 microtile (2 col pairs).
// ---------------------------------------------------------------------------
__global__ __launch_bounds__(256) void out_gemm_kernel(
    const float* __restrict__ Wlin, const float* __restrict__ blin,
    float* __restrict__ out)
{
    __shared__ float As[64][65];    // [row][k]
    __shared__ float Ws[64][66];    // [k][d] (even stride)
    int r0 = blockIdx.x * 64;
    int t  = threadIdx.x;
    int tx = t & 15, ty = t >> 4;
    unsigned long long acc[4][2] = {};

    for (int k0 = 0; k0 < 512; k0 += 64) {
        __syncthreads();
        #pragma unroll
        for (int i = 0; i < 4; i++) {
            int idx = t + i * 256;
            int row = idx >> 4, k4 = idx & 15;
            float4 v = make_float4(0.f, 0.f, 0.f, 0.f);
            if (r0 + row < NN) v = *(const float4*)&g_node[(long)(r0 + row) * 512 + k0 + k4 * 4];
            As[row][k4*4+0] = v.x; As[row][k4*4+1] = v.y;
            As[row][k4*4+2] = v.z; As[row][k4*4+3] = v.w;
            float4 w = *(const float4*)&Wlin[(long)row * 512 + k0 + k4 * 4];  // row = out dim d
            Ws[k4*4+0][row] = w.x; Ws[k4*4+1][row] = w.y;
            Ws[k4*4+2][row] = w.z; Ws[k4*4+3][row] = w.w;
        }
        __syncthreads();
        #pragma unroll 8
        for (int k = 0; k < 64; k++) {
            unsigned long long a[4], b[2];
            #pragma unroll
            for (int i = 0; i < 4; i++) {
                float av = As[ty * 4 + i][k];
                a[i] = pack2(av, av);
            }
            #pragma unroll
            for (int p = 0; p < 2; p++)
                b[p] = *reinterpret_cast<const unsigned long long*>(&Ws[k][tx * 2 + 32 * p]);
            #pragma unroll
            for (int i = 0; i < 4; i++)
                #pragma unroll
                for (int p = 0; p < 2; p++)
                    ffma2(acc[i][p], a[i], b[p]);
        }
    }

    #pragma unroll
    for (int i = 0; i < 4; i++) {
        int row = r0 + ty * 4 + i;
        if (row < NN) {
            #pragma unroll
            for (int p = 0; p < 2; p++) {
                int d = tx * 2 + 32 * p;
                float2 r = unpack2(acc[i][p]);
                float2 o = make_float2(r.x + blin[d], r.y + blin[d + 1]);
                *(float2*)&out[(long)row * 64 + d] = o;
            }
        }
    }
}

// ---------------------------------------------------------------------------
extern "C" void kernel_launch(void* const* d_in, const int* in_sizes, int n_in,
                              void* d_out, int out_size)
{
    const float* x    = (const float*)d_in[0];
    const float* ef   = (const float*)d_in[1];
    const float* Wq   = (const float*)d_in[2];
    const float* bq   = (const float*)d_in[3];
    const float* Wk   = (const float*)d_in[4];
    const float* bk   = (const float*)d_in[5];
    const float* Wv   = (const float*)d_in[6];
    const float* bv   = (const float*)d_in[7];
    const float* Wlin = (const float*)d_in[8];
    const float* blin = (const float*)d_in[9];
    const float* Weq  = (const float*)d_in[10];
    const float* beq  = (const float*)d_in[11];
    const float* Wev  = (const float*)d_in[12];
    const float* bev  = (const float*)d_in[13];
    const float* Wek  = (const float*)d_in[14];
    const float* bek  = (const float*)d_in[15];
    const float* Wel  = (const float*)d_in[16];
    const float* bel  = (const float*)d_in[17];
    const float* Wele = (const float*)d_in[18];
    const float* bele = (const float*)d_in[19];
    const int*   eidx = (const int*)d_in[20];
    float* out = (float*)d_out;

    proj_qkv_kernel<<<dim3(12, 157), 256>>>(x, Wq, bq, Wk, bk, Wv, bv);
    node_edge_kernel<<<NN, 256>>>(ef, eidx, Weq, beq, Wev, bev, Wek, bek,
                                  Wel, bel, Wele, bele, out + NN * 64);
    out_gemm_kernel<<<157, 256>>>(Wlin, blin, out);
}

// round 3
// speedup vs baseline: 1.9595x; 1.5839x over previous
#include <cuda_runtime.h>

#define NN 10000     // nodes
#define KD 8         // out-degree
#define EE 80000     // edges
#define HDIM 512     // H*D
#define NPB 4        // nodes per block in node_edge

// Scratch (allocation-free rule: __device__ globals)
__device__ float g_nq[NN * HDIM];
__device__ float g_nk[NN * HDIM];
__device__ float g_nv[NN * HDIM];
__device__ float g_node[NN * HDIM];

// ---- packed f32x2 helpers (FFMA2 path: only reachable via PTX) ----
__device__ __forceinline__ unsigned long long pack2(float lo, float hi) {
    unsigned long long r;
    asm("mov.b64 %0, {%1, %2};" : "=l"(r) : "f"(lo), "f"(hi));
    return r;
}
__device__ __forceinline__ void ffma2(unsigned long long& d,
                                      unsigned long long a,
                                      unsigned long long b) {
    asm("fma.rn.f32x2 %0, %1, %2, %0;" : "+l"(d) : "l"(a), "l"(b));
}
__device__ __forceinline__ float2 unpack2(unsigned long long v) {
    float2 f;
    asm("mov.b64 {%0, %1}, %2;" : "=f"(f.x), "=f"(f.y) : "l"(v));
    return f;
}

// group barrier: named bar per 64-thread node group
#define GBAR(s) asm volatile("bar.sync %0, %1;" :: "r"((s)+1), "r"(64) : "memory")

// ---------------------------------------------------------------------------
// Kernel 1: fused QKV projection.  out = X[10000,64] @ W^T[64,512] + b.
// 64x128 tile, 4x8 microtile, f32x2 FMA, float4 A loads (4 k per LDS.128).
// ---------------------------------------------------------------------------
__global__ __launch_bounds__(256) void proj_qkv_kernel(
    const float* __restrict__ X,
    const float* __restrict__ Wq, const float* __restrict__ bq,
    const float* __restrict__ Wk, const float* __restrict__ bk,
    const float* __restrict__ Wv, const float* __restrict__ bv)
{
    __shared__ float As[64][68];     // [row][k], 16B-aligned rows
    __shared__ float Bs[64][128];    // [k][col]

    int bx  = blockIdx.x;
    int sel = bx >> 2;
    int c0  = (bx & 3) * 128;
    int r0  = blockIdx.y * 64;
    int t   = threadIdx.x;

    const float* W    = (sel == 0) ? Wq : (sel == 1) ? Wk : Wv;
    const float* bias = (sel == 0) ? bq : (sel == 1) ? bk : bv;
    float*       outp = (sel == 0) ? g_nq : (sel == 1) ? g_nk : g_nv;

    #pragma unroll
    for (int i = 0; i < 4; i++) {
        int idx = t + i * 256;
        int row = idx >> 4, k4 = idx & 15;
        float4 v = make_float4(0.f, 0.f, 0.f, 0.f);
        if (r0 + row < NN) v = *(const float4*)&X[(r0 + row) * 64 + k4 * 4];
        *(float4*)&As[row][k4 * 4] = v;
    }
    #pragma unroll
    for (int i = 0; i < 8; i++) {
        int idx = t + i * 256;
        int c = idx >> 4, k4 = idx & 15;
        float4 w = *(const float4*)&W[(c0 + c) * 64 + k4 * 4];
        Bs[k4*4+0][c] = w.x; Bs[k4*4+1][c] = w.y;
        Bs[k4*4+2][c] = w.z; Bs[k4*4+3][c] = w.w;
    }
    __syncthreads();

    int tx = t & 15, ty = t >> 4;
    unsigned long long acc[4][4] = {};

    #pragma unroll
    for (int k0 = 0; k0 < 64; k0 += 4) {
        float4 a4[4];
        #pragma unroll
        for (int i = 0; i < 4; i++) a4[i] = *(const float4*)&As[ty * 4 + i][k0];
        #pragma unroll
        for (int kk = 0; kk < 4; kk++) {
            unsigned long long a[4], b[4];
            #pragma unroll
            for (int i = 0; i < 4; i++) {
                float av = ((const float*)&a4[i])[kk];
                a[i] = pack2(av, av);
            }
            #pragma unroll
            for (int p = 0; p < 4; p++)
                b[p] = *reinterpret_cast<const unsigned long long*>(&Bs[k0 + kk][tx * 2 + 32 * p]);
            #pragma unroll
            for (int i = 0; i < 4; i++)
                #pragma unroll
                for (int p = 0; p < 4; p++)
                    ffma2(acc[i][p], a[i], b[p]);
        }
    }

    #pragma unroll
    for (int i = 0; i < 4; i++) {
        int row = r0 + ty * 4 + i;
        if (row < NN) {
            #pragma unroll
            for (int p = 0; p < 4; p++) {
                int c = c0 + tx * 2 + 32 * p;
                float2 r = unpack2(acc[i][p]);
                float2 o = make_float2(r.x + bias[c], r.y + bias[c + 1]);
                *(float2*)&outp[(long)row * HDIM + c] = o;
            }
        }
    }
}

// ---------------------------------------------------------------------------
// Kernel 2: fused per-node pipeline. 4 nodes/block, 64 threads per node,
// named barriers only (no block-wide sync inside the pipeline).
// ---------------------------------------------------------------------------
__global__ __launch_bounds__(256) void node_edge_kernel(
    const float* __restrict__ edge_features,
    const int*   __restrict__ edge_index,
    const float* __restrict__ Weq, const float* __restrict__ beq,
    const float* __restrict__ Wev, const float* __restrict__ bev,
    const float* __restrict__ Wek, const float* __restrict__ bek,
    const float* __restrict__ Wel, const float* __restrict__ bel,
    const float* __restrict__ Wele, const float* __restrict__ bele,
    float* __restrict__ out_edge)
{
    // weights staged once per block (padded, conflict-free)
    __shared__ float s_Weq[64][17];
    __shared__ float s_Wev[64][17];
    __shared__ float s_Wek[64][9];
    __shared__ float s_Wel[8][65];
    __shared__ float s_Wele[16][9];
    // per-node state
    __shared__ float s_ef[NPB][8][16];
    __shared__ float s_sqk[NPB][8][8];
    __shared__ float s_eqS[NPB][8][66];   // eq, later reused as eout
    __shared__ float s_evS[NPB][8][66];
    __shared__ float s_ekS[NPB][8][66];
    __shared__ float s_att[NPB][8][4][8];
    __shared__ float s_ee[NPB][8][9];
    __shared__ float s_attn[NPB][8][9];
    __shared__ int   s_e1[NPB][8];

    int t   = threadIdx.x;
    int sub = t >> 6;
    int u   = t & 63;
    int lane = u & 31;
    int w2  = u >> 5;
    int n   = blockIdx.x * NPB + sub;

    // ---- stage weights (cooperative, whole block) ----
    for (int i = t; i < 1024; i += 256) {
        s_Weq[i >> 4][i & 15] = Weq[i];
        s_Wev[i >> 4][i & 15] = Wev[i];
    }
    for (int i = t; i < 512; i += 256) {
        s_Wek[i >> 3][i & 7] = Wek[i];
        s_Wel[i >> 6][i & 63] = Wel[i];
    }
    if (t < 128) s_Wele[t >> 3][t & 7] = Wele[t];

    // ---- per-group loads ----
    if (u < 8)  s_e1[sub][u] = edge_index[EE + n * 8 + u];
    if (u < 32) ((float4*)&s_ef[sub][0][0])[u] =
                    ((const float4*)(edge_features + (long)n * 128))[u];
    GBAR(sub);

    // ---- phase 1: sqk[j][h] = <nq[n,h,:], nk[e1[j],h,:]> / 8 ----
    {
        float4 q4[4];
        const float4* qp = (const float4*)(g_nq + (long)n * 512);
        #pragma unroll
        for (int i = 0; i < 4; i++) q4[i] = qp[lane + 32 * i];
        #pragma unroll
        for (int jj = 0; jj < 4; jj++) {
            int j = w2 * 4 + jj;
            const float4* kp = (const float4*)(g_nk + (long)s_e1[sub][j] * 512);
            float p[4];
            #pragma unroll
            for (int i = 0; i < 4; i++) {
                float4 kv = __ldg(&kp[lane + 32 * i]);
                p[i] = q4[i].x * kv.x + q4[i].y * kv.y + q4[i].z * kv.z + q4[i].w * kv.w;
            }
            #pragma unroll
            for (int m = 1; m < 16; m <<= 1)
                #pragma unroll
                for (int i = 0; i < 4; i++)
                    p[i] += __shfl_xor_sync(0xffffffffu, p[i], m);
            if ((lane & 15) == 0) {
                int hp = lane >> 4;     // h parity
                #pragma unroll
                for (int i = 0; i < 4; i++)
                    s_sqk[sub][j][2 * i + hp] = p[i] * 0.125f;
            }
        }
    }
    __syncthreads();   // covers staged weights + this group's sqk

    // ---- phase 2: eq/ev/ek projections. thread u owns output column u ----
    {
        float wq[16], wv[16], wk8[8];
        #pragma unroll
        for (int c = 0; c < 16; c++) { wq[c] = s_Weq[u][c]; wv[c] = s_Wev[u][c]; }
        #pragma unroll
        for (int c = 0; c < 8; c++) wk8[c] = s_Wek[u][c];
        float bq_ = beq[u], bv_ = bev[u], bk_ = bek[u];
        #pragma unroll
        for (int j = 0; j < 8; j++) {
            float aq = bq_, av = bv_, ak = bk_;
            #pragma unroll
            for (int c = 0; c < 16; c++) {
                float f = s_ef[sub][j][c];
                aq = fmaf(f, wq[c], aq);
                av = fmaf(f, wv[c], av);
            }
            #pragma unroll
            for (int c = 0; c < 8; c++)
                ak = fmaf(s_sqk[sub][j][c], wk8[c], ak);
            s_eqS[sub][j][u] = aq;
            s_evS[sub][j][u] = av;
            s_ekS[sub][j][u] = ak;
        }
    }
    GBAR(sub);

    // ---- phase 3: edge-edge attention. thread u = (q=u>>3, k=u&7) ----
    {
        int q = u >> 3, k = u & 7;
        #pragma unroll
        for (int eh = 0; eh < 4; eh++) {
            float s = 0.f;
            #pragma unroll
            for (int de = 0; de < 16; de++)
                s += s_eqS[sub][q][eh * 16 + de] * s_ekS[sub][k][eh * 16 + de];
            s *= 0.25f;
            float mx = s;
            mx = fmaxf(mx, __shfl_xor_sync(0xffffffffu, mx, 1));
            mx = fmaxf(mx, __shfl_xor_sync(0xffffffffu, mx, 2));
            mx = fmaxf(mx, __shfl_xor_sync(0xffffffffu, mx, 4));
            float ex = expf(s - mx);
            float sm = ex;
            sm += __shfl_xor_sync(0xffffffffu, sm, 1);
            sm += __shfl_xor_sync(0xffffffffu, sm, 2);
            sm += __shfl_xor_sync(0xffffffffu, sm, 4);
            s_att[sub][q][eh][k] = ex / (sm + 1e-16f);
        }
    }
    GBAR(sub);

    // ---- phase 4: eout[q][u] = sum_k att[q][eh(u)][k] * ev[k][u]  (into eqS) ----
    {
        int eh = u >> 4;
        #pragma unroll
        for (int q = 0; q < 8; q++) {
            float acc = 0.f;
            #pragma unroll
            for (int k = 0; k < 8; k++)
                acc = fmaf(s_att[sub][q][eh][k], s_evS[sub][k][u], acc);
            s_eqS[sub][q][u] = acc;
        }
    }
    GBAR(sub);

    // ---- phase 5: edge_emb[q][h] ----
    {
        int q = u >> 3, h = u & 7;
        float acc = bel[h];
        #pragma unroll
        for (int c = 0; c < 64; c++)
            acc = fmaf(s_eqS[sub][q][c], s_Wel[h][c], acc);
        s_ee[sub][q][h] = acc;
    }
    GBAR(sub);

    // ---- phase 6a: node softmax; 6b: edge_embeddings output ----
    if (u < 8) {
        int h = u;
        float l[8], mx = -1e30f;
        #pragma unroll
        for (int j = 0; j < 8; j++) {
            l[j] = s_ee[sub][j][h] + s_sqk[sub][j][h];
            mx = fmaxf(mx, l[j]);
        }
        float sm = 0.f;
        #pragma unroll
        for (int j = 0; j < 8; j++) { l[j] = expf(l[j] - mx); sm += l[j]; }
        float inv = 1.f / (sm + 1e-16f);
        #pragma unroll
        for (int j = 0; j < 8; j++) s_attn[sub][j][h] = l[j] * inv;
    }
    {
        int q = u >> 3, d2 = (u & 7) * 2;
        float a0 = bele[d2], a1 = bele[d2 + 1];
        #pragma unroll
        for (int h = 0; h < 8; h++) {
            float e = s_ee[sub][q][h];
            a0 = fmaf(e, s_Wele[d2][h], a0);
            a1 = fmaf(e, s_Wele[d2 + 1][h], a1);
        }
        *(float2*)&out_edge[(n * 8 + q) * 16 + d2] = make_float2(a0, a1);
    }
    GBAR(sub);

    // ---- phase 7: node aggregation (coalesced float2) ----
    {
        #pragma unroll
        for (int i = 0; i < 4; i++) {
            int c2 = i * 64 + u;         // float2 column
            int h  = c2 >> 5;
            float2 acc = make_float2(0.f, 0.f);
            #pragma unroll
            for (int j = 0; j < 8; j++) {
                float w = s_attn[sub][j][h];
                float2 v = __ldg((const float2*)(g_nv + (long)s_e1[sub][j] * 512) + c2);
                acc.x = fmaf(w, v.x, acc.x);
                acc.y = fmaf(w, v.y, acc.y);
            }
            *(float2*)(g_node + (long)n * 512 + 2 * c2) = acc;
        }
    }
}

// ---------------------------------------------------------------------------
// Kernel 3: node_embeddings = g_node[10000,512] @ Wlin^T[512,64] + blin
// ---------------------------------------------------------------------------
__global__ __launch_bounds__(256) void out_gemm_kernel(
    const float* __restrict__ Wlin, const float* __restrict__ blin,
    float* __restrict__ out)
{
    __shared__ float As[64][68];    // [row][k]
    __shared__ float Ws[64][66];    // [k][d]
    int r0 = blockIdx.x * 64;
    int t  = threadIdx.x;
    int tx = t & 15, ty = t >> 4;
    unsigned long long acc[4][2] = {};

    for (int k0g = 0; k0g < 512; k0g += 64) {
        __syncthreads();
        #pragma unroll
        for (int i = 0; i < 4; i++) {
            int idx = t + i * 256;
            int row = idx >> 4, k4 = idx & 15;
            float4 v = make_float4(0.f, 0.f, 0.f, 0.f);
            if (r0 + row < NN) v = *(const float4*)&g_node[(long)(r0 + row) * 512 + k0g + k4 * 4];
            *(float4*)&As[row][k4 * 4] = v;
            float4 w = *(const float4*)&Wlin[(long)row * 512 + k0g + k4 * 4];  // row = out dim
            Ws[k4*4+0][row] = w.x; Ws[k4*4+1][row] = w.y;
            Ws[k4*4+2][row] = w.z; Ws[k4*4+3][row] = w.w;
        }
        __syncthreads();
        #pragma unroll
        for (int k0 = 0; k0 < 64; k0 += 4) {
            float4 a4[4];
            #pragma unroll
            for (int i = 0; i < 4; i++) a4[i] = *(const float4*)&As[ty * 4 + i][k0];
            #pragma unroll
            for (int kk = 0; kk < 4; kk++) {
                unsigned long long a[4], b[2];
                #pragma unroll
                for (int i = 0; i < 4; i++) {
                    float av = ((const float*)&a4[i])[kk];
                    a[i] = pack2(av, av);
                }
                #pragma unroll
                for (int p = 0; p < 2; p++)
                    b[p] = *reinterpret_cast<const unsigned long long*>(&Ws[k0 + kk][tx * 2 + 32 * p]);
                #pragma unroll
                for (int i = 0; i < 4; i++)
                    #pragma unroll
                    for (int p = 0; p < 2; p++)
                        ffma2(acc[i][p], a[i], b[p]);
            }
        }
    }

    #pragma unroll
    for (int i = 0; i < 4; i++) {
        int row = r0 + ty * 4 + i;
        if (row < NN) {
            #pragma unroll
            for (int p = 0; p < 2; p++) {
                int d = tx * 2 + 32 * p;
                float2 r = unpack2(acc[i][p]);
                float2 o = make_float2(r.x + blin[d], r.y + blin[d + 1]);
                *(float2*)&out[(long)row * 64 + d] = o;
            }
        }
    }
}

// ---------------------------------------------------------------------------
extern "C" void kernel_launch(void* const* d_in, const int* in_sizes, int n_in,
                              void* d_out, int out_size)
{
    const float* x    = (const float*)d_in[0];
    const float* ef   = (const float*)d_in[1];
    const float* Wq   = (const float*)d_in[2];
    const float* bq   = (const float*)d_in[3];
    const float* Wk   = (const float*)d_in[4];
    const float* bk   = (const float*)d_in[5];
    const float* Wv   = (const float*)d_in[6];
    const float* bv   = (const float*)d_in[7];
    const float* Wlin = (const float*)d_in[8];
    const float* blin = (const float*)d_in[9];
    const float* Weq  = (const float*)d_in[10];
    const float* beq  = (const float*)d_in[11];
    const float* Wev  = (const float*)d_in[12];
    const float* bev  = (const float*)d_in[13];
    const float* Wek  = (const float*)d_in[14];
    const float* bek  = (const float*)d_in[15];
    const float* Wel  = (const float*)d_in[16];
    const float* bel  = (const float*)d_in[17];
    const float* Wele = (const float*)d_in[18];
    const float* bele = (const float*)d_in[19];
    const int*   eidx = (const int*)d_in[20];
    float* out = (float*)d_out;

    proj_qkv_kernel<<<dim3(12, 157), 256>>>(x, Wq, bq, Wk, bk, Wv, bv);
    node_edge_kernel<<<NN / NPB, 256>>>(ef, eidx, Weq, beq, Wev, bev, Wek, bek,
                                        Wel, bel, Wele, bele, out + NN * 64);
    out_gemm_kernel<<<157, 256>>>(Wlin, blin, out);
}

// round 4
// speedup vs baseline: 2.1546x; 1.0996x over previous
#include <cuda_runtime.h>

#define NN 10000     // nodes
#define KD 8         // out-degree
#define EE 80000     // edges
#define HDIM 512     // H*D
#define NPB 4        // nodes per block in node_edge

// Scratch (allocation-free rule: __device__ globals)
__device__ float g_nq[NN * HDIM];
__device__ float g_nk[NN * HDIM];
__device__ float g_nv[NN * HDIM];
__device__ float g_node[NN * HDIM];

// ---- packed f32x2 helpers (FFMA2 path: only reachable via PTX) ----
__device__ __forceinline__ unsigned long long pack2(float lo, float hi) {
    unsigned long long r;
    asm("mov.b64 %0, {%1, %2};" : "=l"(r) : "f"(lo), "f"(hi));
    return r;
}
__device__ __forceinline__ void ffma2(unsigned long long& d,
                                      unsigned long long a,
                                      unsigned long long b) {
    asm("fma.rn.f32x2 %0, %1, %2, %0;" : "+l"(d) : "l"(a), "l"(b));
}
__device__ __forceinline__ float2 unpack2(unsigned long long v) {
    float2 f;
    asm("mov.b64 {%0, %1}, %2;" : "=f"(f.x), "=f"(f.y) : "l"(v));
    return f;
}

// group barrier: named bar per 64-thread node group (ids 1..NPB)
#define GBAR(s) asm volatile("bar.sync %0, %1;" :: "r"((s)+1), "r"(64) : "memory")

// ---------------------------------------------------------------------------
// Kernel 1: fused QKV projection.  out = X[10000,64] @ W^T[64,512] + b.
// 128 threads, 64x128 tile, 8x8 microtile, f32x2 packed FMA.
// grid = (12, 157): bx>>2 selects Q/K/V, bx&3 selects 128-col slab.
// ---------------------------------------------------------------------------
__global__ __launch_bounds__(128) void proj_qkv_kernel(
    const float* __restrict__ X,
    const float* __restrict__ Wq, const float* __restrict__ bq,
    const float* __restrict__ Wk, const float* __restrict__ bk,
    const float* __restrict__ Wv, const float* __restrict__ bv)
{
    __shared__ float As[64][68];     // [row][k]
    __shared__ float Bs[64][132];    // [k][col]

    int bx  = blockIdx.x;
    int sel = bx >> 2;
    int c0  = (bx & 3) * 128;
    int r0  = blockIdx.y * 64;
    int t   = threadIdx.x;

    const float* W    = (sel == 0) ? Wq : (sel == 1) ? Wk : Wv;
    const float* bias = (sel == 0) ? bq : (sel == 1) ? bk : bv;
    float*       outp = (sel == 0) ? g_nq : (sel == 1) ? g_nk : g_nv;

    #pragma unroll
    for (int i = 0; i < 8; i++) {
        int idx = t + i * 128;
        int row = idx >> 4, k4 = idx & 15;
        float4 v = make_float4(0.f, 0.f, 0.f, 0.f);
        if (r0 + row < NN) v = *(const float4*)&X[(r0 + row) * 64 + k4 * 4];
        *(float4*)&As[row][k4 * 4] = v;
    }
    #pragma unroll
    for (int i = 0; i < 16; i++) {
        int idx = t + i * 128;
        int c = idx >> 4, k4 = idx & 15;
        float4 w = *(const float4*)&W[(c0 + c) * 64 + k4 * 4];
        Bs[k4*4+0][c] = w.x; Bs[k4*4+1][c] = w.y;
        Bs[k4*4+2][c] = w.z; Bs[k4*4+3][c] = w.w;
    }
    __syncthreads();

    int tx = t & 15, ty = t >> 4;     // ty in [0,8): 8 rows each
    unsigned long long acc[8][4] = {};

    #pragma unroll
    for (int k0 = 0; k0 < 64; k0 += 4) {
        float4 a4[8];
        #pragma unroll
        for (int i = 0; i < 8; i++) a4[i] = *(const float4*)&As[ty * 8 + i][k0];
        #pragma unroll
        for (int kk = 0; kk < 4; kk++) {
            unsigned long long b[4];
            #pragma unroll
            for (int p = 0; p < 4; p++)
                b[p] = *reinterpret_cast<const unsigned long long*>(&Bs[k0 + kk][tx * 2 + 32 * p]);
            #pragma unroll
            for (int i = 0; i < 8; i++) {
                float av = ((const float*)&a4[i])[kk];
                unsigned long long a = pack2(av, av);
                #pragma unroll
                for (int p = 0; p < 4; p++)
                    ffma2(acc[i][p], a, b[p]);
            }
        }
    }

    float2 bb[4];
    #pragma unroll
    for (int p = 0; p < 4; p++) {
        int c = c0 + tx * 2 + 32 * p;
        bb[p] = make_float2(bias[c], bias[c + 1]);
    }
    #pragma unroll
    for (int i = 0; i < 8; i++) {
        int row = r0 + ty * 8 + i;
        if (row < NN) {
            #pragma unroll
            for (int p = 0; p < 4; p++) {
                int c = c0 + tx * 2 + 32 * p;
                float2 r = unpack2(acc[i][p]);
                *(float2*)&outp[(long)row * HDIM + c] =
                    make_float2(r.x + bb[p].x, r.y + bb[p].y);
            }
        }
    }
}

// ---------------------------------------------------------------------------
// Kernel 2: fused per-node pipeline. 4 nodes/block, 64 threads per node,
// named barriers per group; vectorized smem access throughout.
// ---------------------------------------------------------------------------
__global__ __launch_bounds__(256) void node_edge_kernel(
    const float* __restrict__ edge_features,
    const int*   __restrict__ edge_index,
    const float* __restrict__ Weq, const float* __restrict__ beq,
    const float* __restrict__ Wev, const float* __restrict__ bev,
    const float* __restrict__ Wek, const float* __restrict__ bek,
    const float* __restrict__ Wel, const float* __restrict__ bel,
    const float* __restrict__ Wele, const float* __restrict__ bele,
    float* __restrict__ out_edge)
{
    // weights staged once per block
    __shared__ float s_Weq[64][17];
    __shared__ float s_Wev[64][17];
    __shared__ float s_Wek[64][9];
    __shared__ __align__(16) float s_Wel[8][68];
    __shared__ float s_Wele[16][9];
    // per-node state (pads: 68 == 4 mod 32 -> distinct banks, 16B aligned)
    __shared__ __align__(16) float s_ef[NPB][8][16];
    __shared__ __align__(16) float s_sqk[NPB][8][8];
    __shared__ __align__(16) float s_eqS[NPB][8][68];   // eq, reused as eout
    __shared__ __align__(16) float s_evS[NPB][8][68];
    __shared__ __align__(16) float s_ekS[NPB][8][68];
    __shared__ __align__(16) float s_att[NPB][8][4][8];
    __shared__ float s_ee[NPB][8][9];
    __shared__ float s_attn[NPB][8][9];

    int t    = threadIdx.x;
    int sub  = t >> 6;
    int u    = t & 63;
    int lane = u & 31;
    int w2   = u >> 5;
    int n    = blockIdx.x * NPB + sub;

    // ---- stage weights (cooperative, whole block) ----
    for (int i = t; i < 1024; i += 256) {
        s_Weq[i >> 4][i & 15] = Weq[i];
        s_Wev[i >> 4][i & 15] = Wev[i];
    }
    for (int i = t; i < 512; i += 256) {
        s_Wek[i >> 3][i & 7]  = Wek[i];
        s_Wel[i >> 6][i & 63] = Wel[i];
    }
    if (t < 128) s_Wele[t >> 3][t & 7] = Wele[t];

    // ---- e1 via warp shuffle (no barrier needed) ----
    int ej = (lane < 8) ? edge_index[EE + n * 8 + lane] : 0;
    int e1r[8];
    #pragma unroll
    for (int j = 0; j < 8; j++) e1r[j] = __shfl_sync(0xffffffffu, ej, j);

    // ---- edge features ----
    if (u < 32) ((float4*)&s_ef[sub][0][0])[u] =
                    ((const float4*)(edge_features + (long)n * 128))[u];

    // ---- phase 1: sqk[j][h] = <nq[n,h,:], nk[e1[j],h,:]> / 8 ----
    {
        float4 q4[4];
        const float4* qp = (const float4*)(g_nq + (long)n * 512);
        #pragma unroll
        for (int i = 0; i < 4; i++) q4[i] = qp[lane + 32 * i];
        #pragma unroll
        for (int jj = 0; jj < 4; jj++) {
            int j = w2 * 4 + jj;
            const float4* kp = (const float4*)(g_nk + (long)e1r[j] * 512);
            float p[4];
            #pragma unroll
            for (int i = 0; i < 4; i++) {
                float4 kv = __ldg(&kp[lane + 32 * i]);
                p[i] = q4[i].x * kv.x + q4[i].y * kv.y + q4[i].z * kv.z + q4[i].w * kv.w;
            }
            #pragma unroll
            for (int m = 1; m < 16; m <<= 1)
                #pragma unroll
                for (int i = 0; i < 4; i++)
                    p[i] += __shfl_xor_sync(0xffffffffu, p[i], m);
            if ((lane & 15) == 0) {
                int hp = lane >> 4;
                #pragma unroll
                for (int i = 0; i < 4; i++)
                    s_sqk[sub][j][2 * i + hp] = p[i] * 0.125f;
            }
        }
    }
    __syncthreads();   // weights + s_ef + s_sqk all visible

    // ---- phase 2: eq/ev/ek projections. thread u owns output column u ----
    {
        float wq[16], wv[16], wk8[8];
        #pragma unroll
        for (int c = 0; c < 16; c++) { wq[c] = s_Weq[u][c]; wv[c] = s_Wev[u][c]; }
        #pragma unroll
        for (int c = 0; c < 8; c++) wk8[c] = s_Wek[u][c];
        float bq_ = beq[u], bv_ = bev[u], bk_ = bek[u];
        #pragma unroll
        for (int j = 0; j < 8; j++) {
            const float4* ef4 = (const float4*)&s_ef[sub][j][0];
            const float4* sq4 = (const float4*)&s_sqk[sub][j][0];
            float aq = bq_, av = bv_, ak = bk_;
            #pragma unroll
            for (int c4 = 0; c4 < 4; c4++) {
                float4 f = ef4[c4];
                aq = fmaf(f.x, wq[c4*4+0], aq); aq = fmaf(f.y, wq[c4*4+1], aq);
                aq = fmaf(f.z, wq[c4*4+2], aq); aq = fmaf(f.w, wq[c4*4+3], aq);
                av = fmaf(f.x, wv[c4*4+0], av); av = fmaf(f.y, wv[c4*4+1], av);
                av = fmaf(f.z, wv[c4*4+2], av); av = fmaf(f.w, wv[c4*4+3], av);
            }
            #pragma unroll
            for (int c4 = 0; c4 < 2; c4++) {
                float4 s = sq4[c4];
                ak = fmaf(s.x, wk8[c4*4+0], ak); ak = fmaf(s.y, wk8[c4*4+1], ak);
                ak = fmaf(s.z, wk8[c4*4+2], ak); ak = fmaf(s.w, wk8[c4*4+3], ak);
            }
            s_eqS[sub][j][u] = aq;
            s_evS[sub][j][u] = av;
            s_ekS[sub][j][u] = ak;
        }
    }
    GBAR(sub);

    // ---- phase 3: edge-edge attention. thread u = (q=u>>3, k=u&7) ----
    {
        int q = u >> 3, k = u & 7;
        const float4* eq4 = (const float4*)&s_eqS[sub][q][0];
        const float4* ek4 = (const float4*)&s_ekS[sub][k][0];
        #pragma unroll
        for (int eh = 0; eh < 4; eh++) {
            float s = 0.f;
            #pragma unroll
            for (int c = 0; c < 4; c++) {
                float4 a = eq4[eh * 4 + c];
                float4 b = ek4[eh * 4 + c];
                s += a.x * b.x + a.y * b.y + a.z * b.z + a.w * b.w;
            }
            s *= 0.25f;
            float mx = s;
            mx = fmaxf(mx, __shfl_xor_sync(0xffffffffu, mx, 1));
            mx = fmaxf(mx, __shfl_xor_sync(0xffffffffu, mx, 2));
            mx = fmaxf(mx, __shfl_xor_sync(0xffffffffu, mx, 4));
            float ex = expf(s - mx);
            float sm = ex;
            sm += __shfl_xor_sync(0xffffffffu, sm, 1);
            sm += __shfl_xor_sync(0xffffffffu, sm, 2);
            sm += __shfl_xor_sync(0xffffffffu, sm, 4);
            s_att[sub][q][eh][k] = ex / (sm + 1e-16f);
        }
    }
    GBAR(sub);

    // ---- phase 4: eout[q][u] = sum_k att[q][eh(u)][k] * ev[k][u] (into eqS) ----
    {
        int eh = u >> 4;
        float ev[8];
        #pragma unroll
        for (int k = 0; k < 8; k++) ev[k] = s_evS[sub][k][u];
        #pragma unroll
        for (int q = 0; q < 8; q++) {
            float4 a0 = *(const float4*)&s_att[sub][q][eh][0];
            float4 a1 = *(const float4*)&s_att[sub][q][eh][4];
            float acc = 0.f;
            acc = fmaf(a0.x, ev[0], acc); acc = fmaf(a0.y, ev[1], acc);
            acc = fmaf(a0.z, ev[2], acc); acc = fmaf(a0.w, ev[3], acc);
            acc = fmaf(a1.x, ev[4], acc); acc = fmaf(a1.y, ev[5], acc);
            acc = fmaf(a1.z, ev[6], acc); acc = fmaf(a1.w, ev[7], acc);
            s_eqS[sub][q][u] = acc;
        }
    }
    GBAR(sub);

    // ---- phase 5: edge_emb[q][h] ----
    {
        int q = u >> 3, h = u & 7;
        float acc = bel[h];
        const float4* e4 = (const float4*)&s_eqS[sub][q][0];
        const float4* w4 = (const float4*)&s_Wel[h][0];
        #pragma unroll
        for (int c = 0; c < 16; c++) {
            float4 e = e4[c], w = w4[c];
            acc += e.x * w.x + e.y * w.y + e.z * w.z + e.w * w.w;
        }
        s_ee[sub][q][h] = acc;
    }
    GBAR(sub);

    // ---- phase 6a: node softmax (u<8); 6b: edge_embeddings output ----
    if (u < 8) {
        int h = u;
        float l[8], mx = -1e30f;
        #pragma unroll
        for (int j = 0; j < 8; j++) {
            l[j] = s_ee[sub][j][h] + s_sqk[sub][j][h];
            mx = fmaxf(mx, l[j]);
        }
        float sm = 0.f;
        #pragma unroll
        for (int j = 0; j < 8; j++) { l[j] = expf(l[j] - mx); sm += l[j]; }
        float inv = 1.f / (sm + 1e-16f);
        #pragma unroll
        for (int j = 0; j < 8; j++) s_attn[sub][j][h] = l[j] * inv;
    }
    {
        int q = u >> 3, d2 = (u & 7) * 2;
        float a0 = bele[d2], a1 = bele[d2 + 1];
        #pragma unroll
        for (int h = 0; h < 8; h++) {
            float e = s_ee[sub][q][h];
            a0 = fmaf(e, s_Wele[d2][h], a0);
            a1 = fmaf(e, s_Wele[d2 + 1][h], a1);
        }
        *(float2*)&out_edge[(n * 8 + q) * 16 + d2] = make_float2(a0, a1);
    }
    GBAR(sub);

    // ---- phase 7: node aggregation (coalesced float2) ----
    {
        #pragma unroll
        for (int i = 0; i < 4; i++) {
            int c2 = i * 64 + u;
            int h  = c2 >> 5;
            float2 acc = make_float2(0.f, 0.f);
            #pragma unroll
            for (int j = 0; j < 8; j++) {
                float w = s_attn[sub][j][h];
                float2 v = __ldg((const float2*)(g_nv + (long)e1r[j] * 512) + c2);
                acc.x = fmaf(w, v.x, acc.x);
                acc.y = fmaf(w, v.y, acc.y);
            }
            *(float2*)(g_node + (long)n * 512 + 2 * c2) = acc;
        }
    }
}

// ---------------------------------------------------------------------------
// Kernel 3: node_embeddings = g_node[10000,512] @ Wlin^T[512,64] + blin
// ---------------------------------------------------------------------------
__global__ __launch_bounds__(256) void out_gemm_kernel(
    const float* __restrict__ Wlin, const float* __restrict__ blin,
    float* __restrict__ out)
{
    __shared__ float As[64][68];
    __shared__ float Ws[64][66];
    int r0 = blockIdx.x * 64;
    int t  = threadIdx.x;
    int tx = t & 15, ty = t >> 4;
    unsigned long long acc[4][2] = {};

    for (int k0g = 0; k0g < 512; k0g += 64) {
        __syncthreads();
        #pragma unroll
        for (int i = 0; i < 4; i++) {
            int idx = t + i * 256;
            int row = idx >> 4, k4 = idx & 15;
            float4 v = make_float4(0.f, 0.f, 0.f, 0.f);
            if (r0 + row < NN) v = *(const float4*)&g_node[(long)(r0 + row) * 512 + k0g + k4 * 4];
            *(float4*)&As[row][k4 * 4] = v;
            float4 w = *(const float4*)&Wlin[(long)row * 512 + k0g + k4 * 4];
            Ws[k4*4+0][row] = w.x; Ws[k4*4+1][row] = w.y;
            Ws[k4*4+2][row] = w.z; Ws[k4*4+3][row] = w.w;
        }
        __syncthreads();
        #pragma unroll
        for (int k0 = 0; k0 < 64; k0 += 4) {
            float4 a4[4];
            #pragma unroll
            for (int i = 0; i < 4; i++) a4[i] = *(const float4*)&As[ty * 4 + i][k0];
            #pragma unroll
            for (int kk = 0; kk < 4; kk++) {
                unsigned long long b[2];
                #pragma unroll
                for (int p = 0; p < 2; p++)
                    b[p] = *reinterpret_cast<const unsigned long long*>(&Ws[k0 + kk][tx * 2 + 32 * p]);
                #pragma unroll
                for (int i = 0; i < 4; i++) {
                    float av = ((const float*)&a4[i])[kk];
                    unsigned long long a = pack2(av, av);
                    #pragma unroll
                    for (int p = 0; p < 2; p++)
                        ffma2(acc[i][p], a, b[p]);
                }
            }
        }
    }

    #pragma unroll
    for (int i = 0; i < 4; i++) {
        int row = r0 + ty * 4 + i;
        if (row < NN) {
            #pragma unroll
            for (int p = 0; p < 2; p++) {
                int d = tx * 2 + 32 * p;
                float2 r = unpack2(acc[i][p]);
                *(float2*)&out[(long)row * 64 + d] =
                    make_float2(r.x + blin[d], r.y + blin[d + 1]);
            }
        }
    }
}

// ---------------------------------------------------------------------------
extern "C" void kernel_launch(void* const* d_in, const int* in_sizes, int n_in,
                              void* d_out, int out_size)
{
    const float* x    = (const float*)d_in[0];
    const float* ef   = (const float*)d_in[1];
    const float* Wq   = (const float*)d_in[2];
    const float* bq   = (const float*)d_in[3];
    const float* Wk   = (const float*)d_in[4];
    const float* bk   = (const float*)d_in[5];
    const float* Wv   = (const float*)d_in[6];
    const float* bv   = (const float*)d_in[7];
    const float* Wlin = (const float*)d_in[8];
    const float* blin = (const float*)d_in[9];
    const float* Weq  = (const float*)d_in[10];
    const float* beq  = (const float*)d_in[11];
    const float* Wev  = (const float*)d_in[12];
    const float* bev  = (const float*)d_in[13];
    const float* Wek  = (const float*)d_in[14];
    const float* bek  = (const float*)d_in[15];
    const float* Wel  = (const float*)d_in[16];
    const float* bel  = (const float*)d_in[17];
    const float* Wele = (const float*)d_in[18];
    const float* bele = (const float*)d_in[19];
    const int*   eidx = (const int*)d_in[20];
    float* out = (float*)d_out;

    proj_qkv_kernel<<<dim3(12, 157), 128>>>(x, Wq, bq, Wk, bk, Wv, bv);
    node_edge_kernel<<<NN / NPB, 256>>>(ef, eidx, Weq, beq, Wev, bev, Wek, bek,
                                        Wel, bel, Wele, bele, out + NN * 64);
    out_gemm_kernel<<<157, 256>>>(Wlin, blin, out);
}